// round 6
// baseline (speedup 1.0000x reference)
#include <cuda_runtime.h>
#include <cuda_fp16.h>
#include <math.h>

// Problem constants (fixed by the dataset)
#define N_NODES 80000
#define N_EDGES 1280000
#define FDIM    64
#define SCAN_BLOCKS 313           // ceil(80000 / 256)
#define GEMM_ROWS 256             // rows per GEMM block
#define GEMM_BLOCKS 313           // ceil(80000 / 256)
// dynamic smem: Ws[64][64] + Xst[64][264]
#define GEMM_SMEM ((64 * 64 + 64 * 264) * 4)

// -------- scratch: static __device__ arrays, 16B-aligned for vector access --
__device__ __align__(16) __half g_Yh[N_NODES * FDIM]; // GEMM out (unscaled, fp16)
__device__ __align__(16) float g_A[N_NODES * FDIM];   // hidden activations
__device__ __align__(16) float g_dinv[N_NODES];       // 1/sqrt(1 + indeg)
__device__ __align__(16) int   g_cnt[N_NODES];        // in-degree histogram
__device__ __align__(16) int   g_cur[N_NODES];        // CSR fill cursors
__device__ __align__(16) int   g_rowptr[N_NODES + 1]; // CSR row pointers (dst)
__device__ __align__(16) int   g_col[N_EDGES];        // CSR: src per in-edge
__device__ __align__(16) int   g_bsum[SCAN_BLOCKS];   // scan block partials
__device__ __align__(16) int   g_bbase[SCAN_BLOCKS];  // scan block offsets
__device__            int   g_is64;                   // 1 if edges stored int64

// ---------------------------------------------------------------------------
__device__ __forceinline__ int edge_src(const int* EI, int e, int is64) {
    return is64 ? EI[2 * e] : EI[e];
}
__device__ __forceinline__ int edge_dst(const int* EI, int e, int is64) {
    return is64 ? EI[2 * (N_EDGES + e)] : EI[N_EDGES + e];
}

// zero cnt/cur; last block additionally runs the int64-vs-int32 detector.
// (int64 little-endian with values < 2^31 => all odd int32 words are zero)
__global__ void k_zero_detect(int* __restrict__ cnt, int* __restrict__ cur,
                              const int* __restrict__ EI, int* __restrict__ flag) {
    int i = blockIdx.x * 256 + threadIdx.x;
    if (i < N_NODES) { cnt[i] = 0; cur[i] = 0; }
    if (blockIdx.x == gridDim.x - 1 && threadIdx.x < 64) {
        int t = threadIdx.x;
        int v = EI[2 * t + 1];
        unsigned any = __ballot_sync(0xffffffffu, v != 0);
        __shared__ int nz[2];
        if ((t & 31) == 0) nz[t >> 5] = (any != 0);
        __syncwarp();
        if (t == 32) {   // wait for both warps via separate path
        }
        __syncthreads();
        if (t == 0) *flag = (nz[0] == 0 && nz[1] == 0) ? 1 : 0;
    } else if (blockIdx.x == gridDim.x - 1) {
        __syncthreads();
    }
}

__global__ void k_hist(const int* __restrict__ EI, int* __restrict__ cnt,
                       const int* __restrict__ flag) {
    int e = blockIdx.x * blockDim.x + threadIdx.x;
    if (e < N_EDGES) {
        int d = edge_dst(EI, e, *flag);
        atomicAdd(&cnt[d], 1);
    }
}

// --- 3-phase multi-block exclusive scan of cnt -> rowptr ------------------
__global__ __launch_bounds__(256) void k_scan1(const int* __restrict__ cnt,
                                               int* __restrict__ bsum) {
    int i = blockIdx.x * 256 + threadIdx.x;
    int v = (i < N_NODES) ? cnt[i] : 0;
    #pragma unroll
    for (int off = 16; off > 0; off >>= 1)
        v += __shfl_down_sync(0xffffffffu, v, off);
    __shared__ int w[8];
    if ((threadIdx.x & 31) == 0) w[threadIdx.x >> 5] = v;
    __syncthreads();
    if (threadIdx.x < 8) {
        int s = w[threadIdx.x];
        #pragma unroll
        for (int off = 4; off > 0; off >>= 1)
            s += __shfl_down_sync(0xffu, s, off);
        if (threadIdx.x == 0) bsum[blockIdx.x] = s;
    }
}

__global__ __launch_bounds__(512) void k_scan2(const int* __restrict__ bsum,
                                               int* __restrict__ bbase,
                                               int* __restrict__ rowptr) {
    __shared__ int s[512];
    int t = threadIdx.x;
    int v = (t < SCAN_BLOCKS) ? bsum[t] : 0;
    s[t] = v;
    __syncthreads();
    #pragma unroll
    for (int off = 1; off < 512; off <<= 1) {
        int u = (t >= off) ? s[t - off] : 0;
        __syncthreads();
        s[t] += u;
        __syncthreads();
    }
    if (t < SCAN_BLOCKS) bbase[t] = s[t] - v;   // exclusive
    if (t == 0) rowptr[N_NODES] = N_EDGES;      // total known a priori
}

__global__ __launch_bounds__(256) void k_scan3(const int* __restrict__ cnt,
                                               const int* __restrict__ bbase,
                                               int* __restrict__ rowptr,
                                               float* __restrict__ dinv) {
    __shared__ int s[256];
    int t = threadIdx.x;
    int i = blockIdx.x * 256 + t;
    int v = (i < N_NODES) ? cnt[i] : 0;
    s[t] = v;
    __syncthreads();
    #pragma unroll
    for (int off = 1; off < 256; off <<= 1) {
        int u = (t >= off) ? s[t - off] : 0;
        __syncthreads();
        s[t] += u;
        __syncthreads();
    }
    if (i < N_NODES) {
        rowptr[i] = bbase[blockIdx.x] + s[t] - v;   // exclusive
        dinv[i] = rsqrtf(1.0f + (float)v);
    }
}

__global__ void k_fill(const int* __restrict__ EI,
                       const int* __restrict__ rowptr,
                       int* __restrict__ cur,
                       int* __restrict__ col,
                       const int* __restrict__ flag) {
    int e = blockIdx.x * blockDim.x + threadIdx.x;
    if (e < N_EDGES) {
        int is64 = *flag;
        int s = edge_src(EI, e, is64);
        int d = edge_dst(EI, e, is64);
        int p = rowptr[d] + atomicAdd(&cur[d], 1);
        col[p] = s;
    }
}

// ---------------------------------------------------------------------------
// GEMM: Yh[r] = half( in[r] @ W )   — NO dinv (moved into agg).
// 256-row x 64-col tile per 256-thread block; 8x8 outputs per thread;
// X tile transposed in smem so both operands load as float4.
__global__ __launch_bounds__(256, 2) void k_gemm(const float* __restrict__ in,
                                                 const float* __restrict__ W,
                                                 __half* __restrict__ Yh) {
    extern __shared__ float smem[];
    float (*Ws)[64]   = (float(*)[64])smem;                 // 64 x 64
    float (*Xst)[264] = (float(*)[264])(smem + 64 * 64);    // 64 x 264 (k-major)

    const int tid = threadIdx.x;
    const int tx = tid & 7;        // col group: c0 = tx*8
    const int ty = tid >> 3;       // row group: r0 = ty*8
    const int row0 = blockIdx.x * GEMM_ROWS;

    // Load W (4096 floats) via float4
    {
        const float4* Wg = (const float4*)W;
        float4* Wsh = (float4*)Ws;
        #pragma unroll
        for (int i = 0; i < 4; i++) Wsh[tid + i * 256] = Wg[tid + i * 256];
    }
    // Load X rows [row0, row0+256) transposed into Xst[k][r]
    {
        int r = row0 + tid;
        if (r < N_NODES) {
            const float4* Xr = (const float4*)(in + (size_t)r * FDIM);
            #pragma unroll
            for (int i = 0; i < 16; i++) {
                float4 v = Xr[i];
                Xst[4 * i + 0][tid] = v.x;
                Xst[4 * i + 1][tid] = v.y;
                Xst[4 * i + 2][tid] = v.z;
                Xst[4 * i + 3][tid] = v.w;
            }
        } else {
            #pragma unroll
            for (int i = 0; i < 16; i++) {
                Xst[4 * i + 0][tid] = 0.f;
                Xst[4 * i + 1][tid] = 0.f;
                Xst[4 * i + 2][tid] = 0.f;
                Xst[4 * i + 3][tid] = 0.f;
            }
        }
    }
    __syncthreads();

    const int r0 = ty * 8, c0 = tx * 8;
    float acc[8][8] = {};
    #pragma unroll 4
    for (int k = 0; k < 64; k++) {
        float4 a0 = *(const float4*)&Xst[k][r0];
        float4 a1 = *(const float4*)&Xst[k][r0 + 4];
        float4 b0 = *(const float4*)&Ws[k][c0];
        float4 b1 = *(const float4*)&Ws[k][c0 + 4];
        float a[8] = {a0.x, a0.y, a0.z, a0.w, a1.x, a1.y, a1.z, a1.w};
        float b[8] = {b0.x, b0.y, b0.z, b0.w, b1.x, b1.y, b1.z, b1.w};
        #pragma unroll
        for (int i = 0; i < 8; i++)
            #pragma unroll
            for (int j = 0; j < 8; j++)
                acc[i][j] += a[i] * b[j];
    }

    #pragma unroll
    for (int i = 0; i < 8; i++) {
        int r = row0 + r0 + i;
        if (r < N_NODES) {
            __half2 h0 = __floats2half2_rn(acc[i][0], acc[i][1]);
            __half2 h1 = __floats2half2_rn(acc[i][2], acc[i][3]);
            __half2 h2 = __floats2half2_rn(acc[i][4], acc[i][5]);
            __half2 h3 = __floats2half2_rn(acc[i][6], acc[i][7]);
            uint4 p;
            p.x = *(unsigned*)&h0;
            p.y = *(unsigned*)&h1;
            p.z = *(unsigned*)&h2;
            p.w = *(unsigned*)&h3;
            *(uint4*)(Yh + (size_t)r * FDIM + c0) = p;
        }
    }
}

// ---------------------------------------------------------------------------
// Aggregation: one warp per node; fp16 gather payload, fp32 accumulate.
//   out[i] = maybe_relu( dinv[i]*( dinv[i]*Y[i] + sum_s dinv[s]*Y[s] ) + b )
__global__ __launch_bounds__(256) void k_agg(const __half* __restrict__ Yh,
                                             const int* __restrict__ rowptr,
                                             const int* __restrict__ col,
                                             const float* __restrict__ dinv,
                                             const float* __restrict__ bias,
                                             float* __restrict__ out,
                                             int do_relu) {
    int gw = (blockIdx.x * blockDim.x + threadIdx.x) >> 5;   // warp = node
    int lane = threadIdx.x & 31;
    if (gw >= N_NODES) return;

    const __half2* Y2 = (const __half2*)Yh;   // 32 half2 per row
    float dv = dinv[gw];

    float2 vself = __half22float2(Y2[(size_t)gw * 32 + lane]);
    float2 a0, a1 = {0.f, 0.f}, a2 = {0.f, 0.f}, a3 = {0.f, 0.f};
    a0.x = dv * vself.x;
    a0.y = dv * vself.y;

    int beg = rowptr[gw];
    int end = rowptr[gw + 1];
    for (int j = beg; j < end; j += 32) {
        int idx = j + lane;
        int id = (idx < end) ? col[idx] : 0;
        int cnt = min(32, end - j);
        int t = 0;
        for (; t + 4 <= cnt; t += 4) {
            int s0 = __shfl_sync(0xffffffffu, id, t);
            int s1 = __shfl_sync(0xffffffffu, id, t + 1);
            int s2 = __shfl_sync(0xffffffffu, id, t + 2);
            int s3 = __shfl_sync(0xffffffffu, id, t + 3);
            float d0 = dinv[s0];
            float d1 = dinv[s1];
            float d2 = dinv[s2];
            float d3 = dinv[s3];
            float2 v0 = __half22float2(Y2[(size_t)s0 * 32 + lane]);
            float2 v1 = __half22float2(Y2[(size_t)s1 * 32 + lane]);
            float2 v2 = __half22float2(Y2[(size_t)s2 * 32 + lane]);
            float2 v3 = __half22float2(Y2[(size_t)s3 * 32 + lane]);
            a0.x += d0 * v0.x; a0.y += d0 * v0.y;
            a1.x += d1 * v1.x; a1.y += d1 * v1.y;
            a2.x += d2 * v2.x; a2.y += d2 * v2.y;
            a3.x += d3 * v3.x; a3.y += d3 * v3.y;
        }
        for (; t < cnt; t++) {
            int s0 = __shfl_sync(0xffffffffu, id, t);
            float d0 = dinv[s0];
            float2 v0 = __half22float2(Y2[(size_t)s0 * 32 + lane]);
            a0.x += d0 * v0.x; a0.y += d0 * v0.y;
        }
    }

    float2 acc;
    acc.x = (a0.x + a1.x) + (a2.x + a3.x);
    acc.y = (a0.y + a1.y) + (a2.y + a3.y);

    float2 bv = ((const float2*)bias)[lane];
    float2 r;
    r.x = acc.x * dv + bv.x;
    r.y = acc.y * dv + bv.y;
    if (do_relu) {
        r.x = fmaxf(r.x, 0.0f);
        r.y = fmaxf(r.y, 0.0f);
    }
    ((float2*)out)[(size_t)gw * 32 + lane] = r;
}

// ---------------------------------------------------------------------------
extern "C" void kernel_launch(void* const* d_in, const int* in_sizes, int n_in,
                              void* d_out, int out_size) {
    const float* X  = (const float*)d_in[0];
    const int*   EI = (const int*)d_in[1];   // edge_index (int32; int64 auto-detected)
    const float* W1 = (const float*)d_in[2];
    const float* b1 = (const float*)d_in[3];
    const float* W2 = (const float*)d_in[4];
    const float* b2 = (const float*)d_in[5];
    const float* W3 = (const float*)d_in[6];
    const float* b3 = (const float*)d_in[7];
    float* out = (float*)d_out;

    // One-time resource init (resources only; identical launched work per call)
    static cudaStream_t s2 = nullptr;
    static cudaEvent_t evF = nullptr, evJ = nullptr;
    if (!s2) {
        cudaStreamCreateWithFlags(&s2, cudaStreamNonBlocking);
        cudaEventCreateWithFlags(&evF, cudaEventDisableTiming);
        cudaEventCreateWithFlags(&evJ, cudaEventDisableTiming);
        cudaFuncSetAttribute(k_gemm, cudaFuncAttributeMaxDynamicSharedMemorySize,
                             GEMM_SMEM);
    }

    void *pYh, *pA, *pDinv, *pCnt, *pCur, *pRow, *pCol, *pFlag, *pBs, *pBb;
    cudaGetSymbolAddress(&pYh, g_Yh);
    cudaGetSymbolAddress(&pA, g_A);
    cudaGetSymbolAddress(&pDinv, g_dinv);
    cudaGetSymbolAddress(&pCnt, g_cnt);
    cudaGetSymbolAddress(&pCur, g_cur);
    cudaGetSymbolAddress(&pRow, g_rowptr);
    cudaGetSymbolAddress(&pCol, g_col);
    cudaGetSymbolAddress(&pFlag, g_is64);
    cudaGetSymbolAddress(&pBs, g_bsum);
    cudaGetSymbolAddress(&pBb, g_bbase);
    __half* Yh  = (__half*)pYh;
    float* Ab   = (float*)pA;
    float* dinv = (float*)pDinv;
    int*   cnt  = (int*)pCnt;
    int*   cur  = (int*)pCur;
    int*   row  = (int*)pRow;
    int*   colA = (int*)pCol;
    int*   flag = (int*)pFlag;
    int*   bsum = (int*)pBs;
    int*   bbase= (int*)pBb;

    const int nodeBlocks = (N_NODES + 255) / 256;         // 313
    const int edgeBlocks = (N_EDGES + 255) / 256;
    const int aggBlocks  = (N_NODES * 32 + 255) / 256;    // 10000 (warp/node)

    // --- fork: GEMM1 (depends only on X,W1) runs parallel to structure build
    cudaEventRecord(evF, 0);
    cudaStreamWaitEvent(s2, evF, 0);
    k_gemm<<<GEMM_BLOCKS, 256, GEMM_SMEM, s2>>>(X, W1, Yh);
    cudaEventRecord(evJ, s2);

    // --- structure build (main stream) ---
    k_zero_detect<<<nodeBlocks + 1, 256>>>(cnt, cur, EI, flag);
    k_hist<<<edgeBlocks, 256>>>(EI, cnt, flag);
    k_scan1<<<SCAN_BLOCKS, 256>>>(cnt, bsum);
    k_scan2<<<1, 512>>>(bsum, bbase, row);
    k_scan3<<<SCAN_BLOCKS, 256>>>(cnt, bbase, row, dinv);
    k_fill<<<edgeBlocks, 256>>>(EI, row, cur, colA, flag);

    // --- join, then layer 1 aggregation ---
    cudaStreamWaitEvent(0, evJ, 0);
    k_agg<<<aggBlocks, 256>>>(Yh, row, colA, dinv, b1, Ab, 1);

    // --- layer 2 ---
    k_gemm<<<GEMM_BLOCKS, 256, GEMM_SMEM>>>(Ab, W2, Yh);
    k_agg<<<aggBlocks, 256>>>(Yh, row, colA, dinv, b2, Ab, 1);

    // --- layer 3 (no relu) ---
    k_gemm<<<GEMM_BLOCKS, 256, GEMM_SMEM>>>(Ab, W3, Yh);
    k_agg<<<aggBlocks, 256>>>(Yh, row, colA, dinv, b3, out, 0);
}

// round 7
// speedup vs baseline: 1.0251x; 1.0251x over previous
#include <cuda_runtime.h>
#include <cuda_fp16.h>
#include <math.h>

// Problem constants (fixed by the dataset)
#define N_NODES 80000
#define N_EDGES 1280000
#define FDIM    64
#define SCAN_BLOCKS 313           // ceil(80000 / 256)
#define GEMM_ROWS 256             // rows per GEMM block
#define GEMM_BLOCKS 313           // ceil(80000 / 256)
// dynamic smem: Ws[64][64] + Xst[64][264]
#define GEMM_SMEM ((64 * 64 + 64 * 264) * 4)

// -------- scratch: static __device__ arrays, 16B-aligned for vector access --
__device__ __align__(16) __half g_Yh[N_NODES * FDIM]; // GEMM out (dinv-scaled, fp16)
__device__ __align__(16) float g_A[N_NODES * FDIM];   // hidden activations
__device__ __align__(16) float g_dinv[N_NODES];       // 1/sqrt(1 + indeg)
__device__ __align__(16) int   g_cnt[N_NODES];        // in-degree histogram
__device__ __align__(16) int   g_cur[N_NODES];        // CSR fill cursors
__device__ __align__(16) int   g_rowptr[N_NODES + 1]; // CSR row pointers (dst)
__device__ __align__(16) int   g_col[N_EDGES];        // CSR: src per in-edge
__device__ __align__(16) int   g_bsum[SCAN_BLOCKS];   // scan block partials
__device__ __align__(16) int   g_bbase[SCAN_BLOCKS];  // scan block offsets
__device__            int   g_is64;                   // 1 if edges stored int64

// ---------------------------------------------------------------------------
__device__ __forceinline__ int edge_src(const int* EI, int e, int is64) {
    return is64 ? EI[2 * e] : EI[e];
}
__device__ __forceinline__ int edge_dst(const int* EI, int e, int is64) {
    return is64 ? EI[2 * (N_EDGES + e)] : EI[N_EDGES + e];
}

// zero cnt/cur; block 0 additionally runs the int64-vs-int32 detector.
// (int64 little-endian with values < 2^31 => all odd int32 words are zero)
__global__ void k_zero_detect(int* __restrict__ cnt, int* __restrict__ cur,
                              const int* __restrict__ EI, int* __restrict__ flag) {
    int i = blockIdx.x * 256 + threadIdx.x;
    if (i < N_NODES) { cnt[i] = 0; cur[i] = 0; }
    if (blockIdx.x == 0 && threadIdx.x < 64) {
        int t = threadIdx.x;
        int v = EI[2 * t + 1];
        unsigned any = __ballot_sync(0xffffffffu, v != 0);
        if (t == 0) {
            // combine warp0 result now; warp1's result via second ballot below
        }
        // each warp writes its own verdict; thread 0 of warp 0 reads both after
        __shared__ int nz[2];
        if ((t & 31) == 0) nz[t >> 5] = (any != 0);
        __syncthreads();
        if (t == 0) *flag = (nz[0] == 0 && nz[1] == 0) ? 1 : 0;
    } else if (blockIdx.x == 0) {
        __syncthreads();
    }
}

__global__ void k_hist(const int* __restrict__ EI, int* __restrict__ cnt,
                       const int* __restrict__ flag) {
    int e = blockIdx.x * blockDim.x + threadIdx.x;
    if (e < N_EDGES) {
        int d = edge_dst(EI, e, *flag);
        atomicAdd(&cnt[d], 1);
    }
}

// --- 3-phase multi-block exclusive scan of cnt -> rowptr ------------------
__global__ __launch_bounds__(256) void k_scan1(const int* __restrict__ cnt,
                                               int* __restrict__ bsum) {
    int i = blockIdx.x * 256 + threadIdx.x;
    int v = (i < N_NODES) ? cnt[i] : 0;
    #pragma unroll
    for (int off = 16; off > 0; off >>= 1)
        v += __shfl_down_sync(0xffffffffu, v, off);
    __shared__ int w[8];
    if ((threadIdx.x & 31) == 0) w[threadIdx.x >> 5] = v;
    __syncthreads();
    if (threadIdx.x < 8) {
        int s = w[threadIdx.x];
        #pragma unroll
        for (int off = 4; off > 0; off >>= 1)
            s += __shfl_down_sync(0xffu, s, off);
        if (threadIdx.x == 0) bsum[blockIdx.x] = s;
    }
}

__global__ __launch_bounds__(512) void k_scan2(const int* __restrict__ bsum,
                                               int* __restrict__ bbase,
                                               int* __restrict__ rowptr) {
    __shared__ int s[512];
    int t = threadIdx.x;
    int v = (t < SCAN_BLOCKS) ? bsum[t] : 0;
    s[t] = v;
    __syncthreads();
    #pragma unroll
    for (int off = 1; off < 512; off <<= 1) {
        int u = (t >= off) ? s[t - off] : 0;
        __syncthreads();
        s[t] += u;
        __syncthreads();
    }
    if (t < SCAN_BLOCKS) bbase[t] = s[t] - v;   // exclusive
    if (t == 0) rowptr[N_NODES] = N_EDGES;      // total known a priori
}

__global__ __launch_bounds__(256) void k_scan3(const int* __restrict__ cnt,
                                               const int* __restrict__ bbase,
                                               int* __restrict__ rowptr,
                                               float* __restrict__ dinv) {
    __shared__ int s[256];
    int t = threadIdx.x;
    int i = blockIdx.x * 256 + t;
    int v = (i < N_NODES) ? cnt[i] : 0;
    s[t] = v;
    __syncthreads();
    #pragma unroll
    for (int off = 1; off < 256; off <<= 1) {
        int u = (t >= off) ? s[t - off] : 0;
        __syncthreads();
        s[t] += u;
        __syncthreads();
    }
    if (i < N_NODES) {
        rowptr[i] = bbase[blockIdx.x] + s[t] - v;   // exclusive
        dinv[i] = rsqrtf(1.0f + (float)v);
    }
}

__global__ void k_fill(const int* __restrict__ EI,
                       const int* __restrict__ rowptr,
                       int* __restrict__ cur,
                       int* __restrict__ col,
                       const int* __restrict__ flag) {
    int e = blockIdx.x * blockDim.x + threadIdx.x;
    if (e < N_EDGES) {
        int is64 = *flag;
        int s = edge_src(EI, e, is64);
        int d = edge_dst(EI, e, is64);
        int p = rowptr[d] + atomicAdd(&cur[d], 1);
        col[p] = s;
    }
}

// ---------------------------------------------------------------------------
// GEMM: Yh[r] = half( (in[r] @ W) * dinv[r] )
// 256-row x 64-col tile per 256-thread block; 8x8 outputs per thread;
// X tile transposed in smem so both operands load as float4.
__global__ __launch_bounds__(256, 2) void k_gemm(const float* __restrict__ in,
                                                 const float* __restrict__ W,
                                                 const float* __restrict__ dinv,
                                                 __half* __restrict__ Yh) {
    extern __shared__ float smem[];
    float (*Ws)[64]   = (float(*)[64])smem;                 // 64 x 64
    float (*Xst)[264] = (float(*)[264])(smem + 64 * 64);    // 64 x 264 (k-major)

    const int tid = threadIdx.x;
    const int tx = tid & 7;        // col group: c0 = tx*8
    const int ty = tid >> 3;       // row group: r0 = ty*8
    const int row0 = blockIdx.x * GEMM_ROWS;

    // Load W (4096 floats) via float4
    {
        const float4* Wg = (const float4*)W;
        float4* Wsh = (float4*)Ws;
        #pragma unroll
        for (int i = 0; i < 4; i++) Wsh[tid + i * 256] = Wg[tid + i * 256];
    }
    // Load X rows [row0, row0+256) transposed into Xst[k][r]
    {
        int r = row0 + tid;
        if (r < N_NODES) {
            const float4* Xr = (const float4*)(in + (size_t)r * FDIM);
            #pragma unroll
            for (int i = 0; i < 16; i++) {
                float4 v = Xr[i];
                Xst[4 * i + 0][tid] = v.x;
                Xst[4 * i + 1][tid] = v.y;
                Xst[4 * i + 2][tid] = v.z;
                Xst[4 * i + 3][tid] = v.w;
            }
        } else {
            #pragma unroll
            for (int i = 0; i < 16; i++) {
                Xst[4 * i + 0][tid] = 0.f;
                Xst[4 * i + 1][tid] = 0.f;
                Xst[4 * i + 2][tid] = 0.f;
                Xst[4 * i + 3][tid] = 0.f;
            }
        }
    }
    __syncthreads();

    const int r0 = ty * 8, c0 = tx * 8;
    float acc[8][8] = {};
    #pragma unroll 4
    for (int k = 0; k < 64; k++) {
        float4 a0 = *(const float4*)&Xst[k][r0];
        float4 a1 = *(const float4*)&Xst[k][r0 + 4];
        float4 b0 = *(const float4*)&Ws[k][c0];
        float4 b1 = *(const float4*)&Ws[k][c0 + 4];
        float a[8] = {a0.x, a0.y, a0.z, a0.w, a1.x, a1.y, a1.z, a1.w};
        float b[8] = {b0.x, b0.y, b0.z, b0.w, b1.x, b1.y, b1.z, b1.w};
        #pragma unroll
        for (int i = 0; i < 8; i++)
            #pragma unroll
            for (int j = 0; j < 8; j++)
                acc[i][j] += a[i] * b[j];
    }

    #pragma unroll
    for (int i = 0; i < 8; i++) {
        int r = row0 + r0 + i;
        if (r < N_NODES) {
            float dv = dinv[r];
            __half2 h0 = __floats2half2_rn(acc[i][0] * dv, acc[i][1] * dv);
            __half2 h1 = __floats2half2_rn(acc[i][2] * dv, acc[i][3] * dv);
            __half2 h2 = __floats2half2_rn(acc[i][4] * dv, acc[i][5] * dv);
            __half2 h3 = __floats2half2_rn(acc[i][6] * dv, acc[i][7] * dv);
            uint4 p;
            p.x = *(unsigned*)&h0;
            p.y = *(unsigned*)&h1;
            p.z = *(unsigned*)&h2;
            p.w = *(unsigned*)&h3;
            *(uint4*)(Yh + (size_t)r * FDIM + c0) = p;
        }
    }
}

// ---------------------------------------------------------------------------
// Aggregation: one warp per node; fp16 gather payload, fp32 accumulate.
//   out[i] = maybe_relu( dinv[i] * ( Y[i] + sum_{src in CSR[i]} Y[src] ) + b )
// (Y rows already carry their own dinv factor from the GEMM epilogue.)
__global__ __launch_bounds__(256) void k_agg(const __half* __restrict__ Yh,
                                             const int* __restrict__ rowptr,
                                             const int* __restrict__ col,
                                             const float* __restrict__ dinv,
                                             const float* __restrict__ bias,
                                             float* __restrict__ out,
                                             int do_relu) {
    int gw = (blockIdx.x * blockDim.x + threadIdx.x) >> 5;   // warp = node
    int lane = threadIdx.x & 31;
    if (gw >= N_NODES) return;

    const __half2* Y2 = (const __half2*)Yh;   // 32 half2 per row
    float2 a0 = __half22float2(Y2[(size_t)gw * 32 + lane]);  // self term
    float2 a1 = {0.f, 0.f}, a2 = {0.f, 0.f}, a3 = {0.f, 0.f};

    int beg = rowptr[gw];
    int end = rowptr[gw + 1];
    for (int j = beg; j < end; j += 32) {
        int idx = j + lane;
        int id = (idx < end) ? col[idx] : 0;
        int cnt = min(32, end - j);
        int t = 0;
        for (; t + 8 <= cnt; t += 8) {
            int s0 = __shfl_sync(0xffffffffu, id, t);
            int s1 = __shfl_sync(0xffffffffu, id, t + 1);
            int s2 = __shfl_sync(0xffffffffu, id, t + 2);
            int s3 = __shfl_sync(0xffffffffu, id, t + 3);
            int s4 = __shfl_sync(0xffffffffu, id, t + 4);
            int s5 = __shfl_sync(0xffffffffu, id, t + 5);
            int s6 = __shfl_sync(0xffffffffu, id, t + 6);
            int s7 = __shfl_sync(0xffffffffu, id, t + 7);
            __half2 h0 = Y2[(size_t)s0 * 32 + lane];
            __half2 h1 = Y2[(size_t)s1 * 32 + lane];
            __half2 h2 = Y2[(size_t)s2 * 32 + lane];
            __half2 h3 = Y2[(size_t)s3 * 32 + lane];
            __half2 h4 = Y2[(size_t)s4 * 32 + lane];
            __half2 h5 = Y2[(size_t)s5 * 32 + lane];
            __half2 h6 = Y2[(size_t)s6 * 32 + lane];
            __half2 h7 = Y2[(size_t)s7 * 32 + lane];
            float2 v0 = __half22float2(h0);
            float2 v1 = __half22float2(h1);
            float2 v2 = __half22float2(h2);
            float2 v3 = __half22float2(h3);
            float2 v4 = __half22float2(h4);
            float2 v5 = __half22float2(h5);
            float2 v6 = __half22float2(h6);
            float2 v7 = __half22float2(h7);
            a0.x += v0.x; a0.y += v0.y;
            a1.x += v1.x; a1.y += v1.y;
            a2.x += v2.x; a2.y += v2.y;
            a3.x += v3.x; a3.y += v3.y;
            a0.x += v4.x; a0.y += v4.y;
            a1.x += v5.x; a1.y += v5.y;
            a2.x += v6.x; a2.y += v6.y;
            a3.x += v7.x; a3.y += v7.y;
        }
        for (; t < cnt; t++) {
            int s0 = __shfl_sync(0xffffffffu, id, t);
            float2 v0 = __half22float2(Y2[(size_t)s0 * 32 + lane]);
            a0.x += v0.x; a0.y += v0.y;
        }
    }

    float2 acc;
    acc.x = (a0.x + a1.x) + (a2.x + a3.x);
    acc.y = (a0.y + a1.y) + (a2.y + a3.y);

    float dv = dinv[gw];
    float2 bv = ((const float2*)bias)[lane];
    float2 r;
    r.x = acc.x * dv + bv.x;
    r.y = acc.y * dv + bv.y;
    if (do_relu) {
        r.x = fmaxf(r.x, 0.0f);
        r.y = fmaxf(r.y, 0.0f);
    }
    ((float2*)out)[(size_t)gw * 32 + lane] = r;
}

// ---------------------------------------------------------------------------
extern "C" void kernel_launch(void* const* d_in, const int* in_sizes, int n_in,
                              void* d_out, int out_size) {
    const float* X  = (const float*)d_in[0];
    const int*   EI = (const int*)d_in[1];   // edge_index (int32; int64 auto-detected)
    const float* W1 = (const float*)d_in[2];
    const float* b1 = (const float*)d_in[3];
    const float* W2 = (const float*)d_in[4];
    const float* b2 = (const float*)d_in[5];
    const float* W3 = (const float*)d_in[6];
    const float* b3 = (const float*)d_in[7];
    float* out = (float*)d_out;

    static bool inited = false;
    if (!inited) {
        cudaFuncSetAttribute(k_gemm, cudaFuncAttributeMaxDynamicSharedMemorySize,
                             GEMM_SMEM);
        inited = true;
    }

    void *pYh, *pA, *pDinv, *pCnt, *pCur, *pRow, *pCol, *pFlag, *pBs, *pBb;
    cudaGetSymbolAddress(&pYh, g_Yh);
    cudaGetSymbolAddress(&pA, g_A);
    cudaGetSymbolAddress(&pDinv, g_dinv);
    cudaGetSymbolAddress(&pCnt, g_cnt);
    cudaGetSymbolAddress(&pCur, g_cur);
    cudaGetSymbolAddress(&pRow, g_rowptr);
    cudaGetSymbolAddress(&pCol, g_col);
    cudaGetSymbolAddress(&pFlag, g_is64);
    cudaGetSymbolAddress(&pBs, g_bsum);
    cudaGetSymbolAddress(&pBb, g_bbase);
    __half* Yh  = (__half*)pYh;
    float* Ab   = (float*)pA;
    float* dinv = (float*)pDinv;
    int*   cnt  = (int*)pCnt;
    int*   cur  = (int*)pCur;
    int*   row  = (int*)pRow;
    int*   colA = (int*)pCol;
    int*   flag = (int*)pFlag;
    int*   bsum = (int*)pBs;
    int*   bbase= (int*)pBb;

    const int nodeBlocks = (N_NODES + 255) / 256;         // 313
    const int edgeBlocks = (N_EDGES + 255) / 256;
    const int aggBlocks  = (N_NODES * 32 + 255) / 256;    // 10000 (warp/node)

    // --- structure build ---
    k_zero_detect<<<nodeBlocks, 256>>>(cnt, cur, EI, flag);
    k_hist<<<edgeBlocks, 256>>>(EI, cnt, flag);
    k_scan1<<<SCAN_BLOCKS, 256>>>(cnt, bsum);
    k_scan2<<<1, 512>>>(bsum, bbase, row);
    k_scan3<<<SCAN_BLOCKS, 256>>>(cnt, bbase, row, dinv);
    k_fill<<<edgeBlocks, 256>>>(EI, row, cur, colA, flag);

    // --- layer 1: X -> g_A ---
    k_gemm<<<GEMM_BLOCKS, 256, GEMM_SMEM>>>(X, W1, dinv, Yh);
    k_agg<<<aggBlocks, 256>>>(Yh, row, colA, dinv, b1, Ab, 1);

    // --- layer 2: g_A -> g_A ---
    k_gemm<<<GEMM_BLOCKS, 256, GEMM_SMEM>>>(Ab, W2, dinv, Yh);
    k_agg<<<aggBlocks, 256>>>(Yh, row, colA, dinv, b2, Ab, 1);

    // --- layer 3: g_A -> d_out (no relu) ---
    k_gemm<<<GEMM_BLOCKS, 256, GEMM_SMEM>>>(Ab, W3, dinv, Yh);
    k_agg<<<aggBlocks, 256>>>(Yh, row, colA, dinv, b3, out, 0);
}

// round 8
// speedup vs baseline: 1.1214x; 1.0939x over previous
#include <cuda_runtime.h>
#include <cuda_fp16.h>
#include <math.h>

// Problem constants (fixed by the dataset)
#define N_NODES 80000
#define N_EDGES 1280000
#define FDIM    64
#define SCAN_BLOCKS 157           // ceil(80000 / 512)

// -------- scratch: static __device__ arrays, 16B-aligned for vector access --
__device__ __align__(16) __half g_Yh[N_NODES * FDIM]; // GEMM out (fp16)
__device__ __align__(16) float g_A[N_NODES * FDIM];   // hidden activations
__device__ __align__(16) float g_dinv[N_NODES];       // 1/sqrt(1 + indeg)
__device__ __align__(16) int   g_cnt[N_NODES];        // in-degree; consumed by fill
__device__ __align__(16) int   g_rowptr[N_NODES + 1]; // CSR row pointers (dst)
__device__ __align__(16) int   g_col[N_EDGES];        // CSR: src per in-edge
__device__ __align__(16) int   g_bsum[SCAN_BLOCKS];   // scan block partials
__device__            int   g_is64;                   // 1 if edges stored int64

// ---------------------------------------------------------------------------
__device__ __forceinline__ int edge_src(const int* EI, int e, int is64) {
    return is64 ? EI[2 * e] : EI[e];
}
__device__ __forceinline__ int edge_dst(const int* EI, int e, int is64) {
    return is64 ? EI[2 * (N_EDGES + e)] : EI[N_EDGES + e];
}

// zero cnt; block 0 additionally runs the int64-vs-int32 detector.
// (int64 little-endian with values < 2^31 => every odd int32 word is zero)
__global__ void k_zero_detect(int* __restrict__ cnt,
                              const int* __restrict__ EI, int* __restrict__ flag) {
    int i = blockIdx.x * 256 + threadIdx.x;
    if (i < N_NODES) cnt[i] = 0;
    if (blockIdx.x == 0) {
        __shared__ int nz[2];
        int t = threadIdx.x;
        if (t < 64) {
            int v = EI[2 * t + 1];
            unsigned any = __ballot_sync(0xffffffffu, v != 0);
            if ((t & 31) == 0) nz[t >> 5] = (any != 0);
        }
        __syncthreads();
        if (t == 0) *flag = (nz[0] == 0 && nz[1] == 0) ? 1 : 0;
    }
}

__global__ void k_hist(const int* __restrict__ EI, int* __restrict__ cnt,
                       const int* __restrict__ flag) {
    int e = blockIdx.x * blockDim.x + threadIdx.x;
    if (e < N_EDGES) {
        int d = edge_dst(EI, e, *flag);
        atomicAdd(&cnt[d], 1);
    }
}

// Phase 1: per-block (512 nodes) sums.
__global__ __launch_bounds__(512) void k_scan1(const int* __restrict__ cnt,
                                               int* __restrict__ bsum) {
    int i = blockIdx.x * 512 + threadIdx.x;
    int v = (i < N_NODES) ? cnt[i] : 0;
    #pragma unroll
    for (int off = 16; off > 0; off >>= 1)
        v += __shfl_down_sync(0xffffffffu, v, off);
    __shared__ int w[16];
    if ((threadIdx.x & 31) == 0) w[threadIdx.x >> 5] = v;
    __syncthreads();
    if (threadIdx.x < 16) {
        int s = w[threadIdx.x];
        #pragma unroll
        for (int off = 8; off > 0; off >>= 1)
            s += __shfl_down_sync(0xffffu, s, off);
        if (threadIdx.x == 0) bsum[blockIdx.x] = s;
    }
}

// Phase 2+3 merged: every block scans the 157 partials in smem (redundant,
// cheap), takes its exclusive base, then scans its own 512-node chunk.
// Emits rowptr and dinv.
__global__ __launch_bounds__(512) void k_scan3(const int* __restrict__ cnt,
                                               const int* __restrict__ bsum,
                                               int* __restrict__ rowptr,
                                               float* __restrict__ dinv) {
    __shared__ int s[512];
    __shared__ int base_sh;
    int t = threadIdx.x;

    // scan bsum[0..156] (inclusive) in smem
    int v = (t < SCAN_BLOCKS) ? bsum[t] : 0;
    s[t] = v;
    __syncthreads();
    #pragma unroll
    for (int off = 1; off < 512; off <<= 1) {
        int u = (t >= off) ? s[t - off] : 0;
        __syncthreads();
        s[t] += u;
        __syncthreads();
    }
    if (t == 0) base_sh = (blockIdx.x == 0) ? 0 : s[blockIdx.x - 1];
    __syncthreads();
    int base = base_sh;
    __syncthreads();

    // scan own chunk
    int i = blockIdx.x * 512 + t;
    int c = (i < N_NODES) ? cnt[i] : 0;
    s[t] = c;
    __syncthreads();
    #pragma unroll
    for (int off = 1; off < 512; off <<= 1) {
        int u = (t >= off) ? s[t - off] : 0;
        __syncthreads();
        s[t] += u;
        __syncthreads();
    }
    if (i < N_NODES) {
        rowptr[i] = base + s[t] - c;   // exclusive
        dinv[i] = rsqrtf(1.0f + (float)c);
    }
    if (i == 0) rowptr[N_NODES] = N_EDGES;   // total known a priori
}

// fill: consume cnt as cursors via atomicSub (cnt dead after scan3).
__global__ void k_fill(const int* __restrict__ EI,
                       const int* __restrict__ rowptr,
                       int* __restrict__ cnt,
                       int* __restrict__ col,
                       const int* __restrict__ flag) {
    int e = blockIdx.x * blockDim.x + threadIdx.x;
    if (e < N_EDGES) {
        int is64 = *flag;
        int s = edge_src(EI, e, is64);
        int d = edge_dst(EI, e, is64);
        int p = rowptr[d] + atomicSub(&cnt[d], 1) - 1;
        col[p] = s;
    }
}

// ---------------------------------------------------------------------------
// GEMM: Yh[r] = half( (in[r] @ W) * (dinv ? dinv[r] : 1) )
// 64-row tiles; 16x16 threads; 4x4 outputs/thread. (Proven R4/R5 config.)
__global__ __launch_bounds__(256) void k_gemm(const float* __restrict__ in,
                                              const float* __restrict__ W,
                                              const float* __restrict__ dinv,
                                              __half* __restrict__ Yh) {
    __shared__ __align__(16) float Ws[64][64];
    __shared__ __align__(16) float Xs[64][64];

    const int tx = threadIdx.x;      // 0..15
    const int ty = threadIdx.y;      // 0..15
    const int tid = ty * 16 + tx;    // 0..255
    const int row0 = blockIdx.x * 64;

    const float4* Wg = (const float4*)W;
    const float4* Xg = (const float4*)(in + (size_t)row0 * FDIM);
    float4* Wsh = (float4*)Ws;
    float4* Xsh = (float4*)Xs;
    #pragma unroll
    for (int i = 0; i < 4; i++) {
        Wsh[tid + i * 256] = Wg[tid + i * 256];
        Xsh[tid + i * 256] = Xg[tid + i * 256];
    }
    __syncthreads();

    float acc[4][4] = {};
    #pragma unroll 16
    for (int k = 0; k < 64; k++) {
        float4 b = *(const float4*)&Ws[k][tx * 4];
        #pragma unroll
        for (int i = 0; i < 4; i++) {
            float a = Xs[ty * 4 + i][k];
            acc[i][0] += a * b.x;
            acc[i][1] += a * b.y;
            acc[i][2] += a * b.z;
            acc[i][3] += a * b.w;
        }
    }

    #pragma unroll
    for (int i = 0; i < 4; i++) {
        int r = row0 + ty * 4 + i;
        float dv = dinv ? dinv[r] : 1.0f;
        __half2 h0 = __floats2half2_rn(acc[i][0] * dv, acc[i][1] * dv);
        __half2 h1 = __floats2half2_rn(acc[i][2] * dv, acc[i][3] * dv);
        __half2* dst = (__half2*)(Yh + (size_t)r * FDIM + tx * 4);
        dst[0] = h0;
        dst[1] = h1;
    }
}

// ---------------------------------------------------------------------------
// Scale pass for layer 1: Yh[row] *= dinv[row]  (warp per row)
__global__ __launch_bounds__(256) void k_scale(__half* __restrict__ Yh,
                                               const float* __restrict__ dinv) {
    int w = blockIdx.x * 8 + (threadIdx.x >> 5);
    int lane = threadIdx.x & 31;
    if (w >= N_NODES) return;
    float dv = dinv[w];
    __half2* Y2 = (__half2*)Yh;
    __half2 h = Y2[(size_t)w * 32 + lane];
    float2 f = __half22float2(h);
    Y2[(size_t)w * 32 + lane] = __floats2half2_rn(f.x * dv, f.y * dv);
}

// ---------------------------------------------------------------------------
// Aggregation: one warp per node; fp16 gather payload, fp32 accumulate.
//   out[i] = maybe_relu( dinv[i] * ( Y[i] + sum_{src in CSR[i]} Y[src] ) + b )
__global__ __launch_bounds__(256) void k_agg(const __half* __restrict__ Yh,
                                             const int* __restrict__ rowptr,
                                             const int* __restrict__ col,
                                             const float* __restrict__ dinv,
                                             const float* __restrict__ bias,
                                             float* __restrict__ out,
                                             int do_relu) {
    int gw = (blockIdx.x * blockDim.x + threadIdx.x) >> 5;   // warp = node
    int lane = threadIdx.x & 31;
    if (gw >= N_NODES) return;

    const __half2* Y2 = (const __half2*)Yh;   // 32 half2 per row
    float2 a0 = __half22float2(Y2[(size_t)gw * 32 + lane]);  // self term
    float2 a1 = {0.f, 0.f}, a2 = {0.f, 0.f}, a3 = {0.f, 0.f};

    int beg = rowptr[gw];
    int end = rowptr[gw + 1];
    for (int j = beg; j < end; j += 32) {
        int idx = j + lane;
        int id = (idx < end) ? col[idx] : 0;
        int cnt = min(32, end - j);
        int t = 0;
        for (; t + 8 <= cnt; t += 8) {
            int s0 = __shfl_sync(0xffffffffu, id, t);
            int s1 = __shfl_sync(0xffffffffu, id, t + 1);
            int s2 = __shfl_sync(0xffffffffu, id, t + 2);
            int s3 = __shfl_sync(0xffffffffu, id, t + 3);
            int s4 = __shfl_sync(0xffffffffu, id, t + 4);
            int s5 = __shfl_sync(0xffffffffu, id, t + 5);
            int s6 = __shfl_sync(0xffffffffu, id, t + 6);
            int s7 = __shfl_sync(0xffffffffu, id, t + 7);
            __half2 h0 = Y2[(size_t)s0 * 32 + lane];
            __half2 h1 = Y2[(size_t)s1 * 32 + lane];
            __half2 h2 = Y2[(size_t)s2 * 32 + lane];
            __half2 h3 = Y2[(size_t)s3 * 32 + lane];
            __half2 h4 = Y2[(size_t)s4 * 32 + lane];
            __half2 h5 = Y2[(size_t)s5 * 32 + lane];
            __half2 h6 = Y2[(size_t)s6 * 32 + lane];
            __half2 h7 = Y2[(size_t)s7 * 32 + lane];
            float2 v0 = __half22float2(h0);
            float2 v1 = __half22float2(h1);
            float2 v2 = __half22float2(h2);
            float2 v3 = __half22float2(h3);
            float2 v4 = __half22float2(h4);
            float2 v5 = __half22float2(h5);
            float2 v6 = __half22float2(h6);
            float2 v7 = __half22float2(h7);
            a0.x += v0.x; a0.y += v0.y;
            a1.x += v1.x; a1.y += v1.y;
            a2.x += v2.x; a2.y += v2.y;
            a3.x += v3.x; a3.y += v3.y;
            a0.x += v4.x; a0.y += v4.y;
            a1.x += v5.x; a1.y += v5.y;
            a2.x += v6.x; a2.y += v6.y;
            a3.x += v7.x; a3.y += v7.y;
        }
        for (; t < cnt; t++) {
            int s0 = __shfl_sync(0xffffffffu, id, t);
            float2 v0 = __half22float2(Y2[(size_t)s0 * 32 + lane]);
            a0.x += v0.x; a0.y += v0.y;
        }
    }

    float2 acc;
    acc.x = (a0.x + a1.x) + (a2.x + a3.x);
    acc.y = (a0.y + a1.y) + (a2.y + a3.y);

    float dv = dinv[gw];
    float2 bv = ((const float2*)bias)[lane];
    float2 r;
    r.x = acc.x * dv + bv.x;
    r.y = acc.y * dv + bv.y;
    if (do_relu) {
        r.x = fmaxf(r.x, 0.0f);
        r.y = fmaxf(r.y, 0.0f);
    }
    ((float2*)out)[(size_t)gw * 32 + lane] = r;
}

// ---------------------------------------------------------------------------
extern "C" void kernel_launch(void* const* d_in, const int* in_sizes, int n_in,
                              void* d_out, int out_size) {
    const float* X  = (const float*)d_in[0];
    const int*   EI = (const int*)d_in[1];   // edge_index (int32; int64 auto-detected)
    const float* W1 = (const float*)d_in[2];
    const float* b1 = (const float*)d_in[3];
    const float* W2 = (const float*)d_in[4];
    const float* b2 = (const float*)d_in[5];
    const float* W3 = (const float*)d_in[6];
    const float* b3 = (const float*)d_in[7];
    float* out = (float*)d_out;

    // One-time resources (streams/events only; no device memory).
    static cudaStream_t s2 = nullptr;
    static cudaEvent_t evF = nullptr, evJ = nullptr;
    if (!s2) {
        cudaStreamCreateWithFlags(&s2, cudaStreamNonBlocking);
        cudaEventCreateWithFlags(&evF, cudaEventDisableTiming);
        cudaEventCreateWithFlags(&evJ, cudaEventDisableTiming);
    }

    void *pYh, *pA, *pDinv, *pCnt, *pRow, *pCol, *pFlag, *pBs;
    cudaGetSymbolAddress(&pYh, g_Yh);
    cudaGetSymbolAddress(&pA, g_A);
    cudaGetSymbolAddress(&pDinv, g_dinv);
    cudaGetSymbolAddress(&pCnt, g_cnt);
    cudaGetSymbolAddress(&pRow, g_rowptr);
    cudaGetSymbolAddress(&pCol, g_col);
    cudaGetSymbolAddress(&pFlag, g_is64);
    cudaGetSymbolAddress(&pBs, g_bsum);
    __half* Yh  = (__half*)pYh;
    float* Ab   = (float*)pA;
    float* dinv = (float*)pDinv;
    int*   cnt  = (int*)pCnt;
    int*   row  = (int*)pRow;
    int*   colA = (int*)pCol;
    int*   flag = (int*)pFlag;
    int*   bsum = (int*)pBs;

    const int nodeBlocks = (N_NODES + 255) / 256;         // 313
    const int edgeBlocks = (N_EDGES + 255) / 256;
    const int gemmBlocks = (N_NODES + 63) / 64;           // 1250
    const int aggBlocks  = (N_NODES * 32 + 255) / 256;    // 10000 (warp/node)
    const int scaleBlocks = (N_NODES + 7) / 8;            // warp per row

    // --- fork: GEMM1 (X @ W1, unscaled) runs parallel to structure build ---
    cudaEventRecord(evF, 0);
    cudaStreamWaitEvent(s2, evF, 0);
    k_gemm<<<gemmBlocks, dim3(16, 16), 0, s2>>>(X, W1, nullptr, Yh);
    cudaEventRecord(evJ, s2);

    // --- structure build (main stream) ---
    k_zero_detect<<<nodeBlocks, 256>>>(cnt, EI, flag);
    k_hist<<<edgeBlocks, 256>>>(EI, cnt, flag);
    k_scan1<<<SCAN_BLOCKS, 512>>>(cnt, bsum);
    k_scan3<<<SCAN_BLOCKS, 512>>>(cnt, bsum, row, dinv);
    k_fill<<<edgeBlocks, 256>>>(EI, row, cnt, colA, flag);

    // --- join; apply dinv to layer-1 Y; aggregate ---
    cudaStreamWaitEvent(0, evJ, 0);
    k_scale<<<scaleBlocks, 256>>>(Yh, dinv);
    k_agg<<<aggBlocks, 256>>>(Yh, row, colA, dinv, b1, Ab, 1);

    // --- layer 2 ---
    k_gemm<<<gemmBlocks, dim3(16, 16)>>>(Ab, W2, dinv, Yh);
    k_agg<<<aggBlocks, 256>>>(Yh, row, colA, dinv, b2, Ab, 1);

    // --- layer 3 (no relu) ---
    k_gemm<<<gemmBlocks, dim3(16, 16)>>>(Ab, W3, dinv, Yh);
    k_agg<<<aggBlocks, 256>>>(Yh, row, colA, dinv, b3, out, 0);
}

// round 9
// speedup vs baseline: 1.1659x; 1.0396x over previous
#include <cuda_runtime.h>
#include <cuda_fp16.h>
#include <math.h>

// Problem constants (fixed by the dataset)
#define N_NODES 80000
#define N_EDGES 1280000
#define FDIM    64
#define SCAN_BLOCKS 157           // ceil(80000 / 512)
#define GEMM_ROWS 128
#define GEMM_BLOCKS 625           // 80000 / 128

// -------- scratch: static __device__ arrays, 16B-aligned for vector access --
__device__ __align__(16) __half g_Yh[N_NODES * FDIM]; // GEMM out (dinv-scaled fp16)
__device__ __align__(16) float g_A[N_NODES * FDIM];   // hidden activations
__device__ __align__(16) float g_dinv[N_NODES];       // 1/sqrt(1 + indeg)
__device__ __align__(16) int   g_cnt[N_NODES];        // in-degree; consumed by fill
__device__ __align__(16) int   g_rowptr[N_NODES + 1]; // CSR row pointers (dst)
__device__ __align__(16) int   g_col[N_EDGES];        // CSR: src per in-edge
__device__ __align__(16) int   g_bsum[SCAN_BLOCKS];   // scan block partials
__device__            int   g_is64;                   // 1 if edges stored int64

// ---------------------------------------------------------------------------
__device__ __forceinline__ int edge_src(const int* EI, int e, int is64) {
    return is64 ? EI[2 * e] : EI[e];
}
__device__ __forceinline__ int edge_dst(const int* EI, int e, int is64) {
    return is64 ? EI[2 * (N_EDGES + e)] : EI[N_EDGES + e];
}

// zero cnt; block 0 additionally runs the int64-vs-int32 detector.
__global__ void k_zero_detect(int* __restrict__ cnt,
                              const int* __restrict__ EI, int* __restrict__ flag) {
    int i = blockIdx.x * 256 + threadIdx.x;
    if (i < N_NODES) cnt[i] = 0;
    if (blockIdx.x == 0) {
        __shared__ int nz[2];
        int t = threadIdx.x;
        if (t < 64) {
            int v = EI[2 * t + 1];
            unsigned any = __ballot_sync(0xffffffffu, v != 0);
            if ((t & 31) == 0) nz[t >> 5] = (any != 0);
        }
        __syncthreads();
        if (t == 0) *flag = (nz[0] == 0 && nz[1] == 0) ? 1 : 0;
    }
}

__global__ void k_hist(const int* __restrict__ EI, int* __restrict__ cnt,
                       const int* __restrict__ flag) {
    int e = blockIdx.x * blockDim.x + threadIdx.x;
    if (e < N_EDGES) {
        int d = edge_dst(EI, e, *flag);
        atomicAdd(&cnt[d], 1);
    }
}

// Phase 1: per-block (512 nodes) sums.
__global__ __launch_bounds__(512) void k_scan1(const int* __restrict__ cnt,
                                               int* __restrict__ bsum) {
    int i = blockIdx.x * 512 + threadIdx.x;
    int v = (i < N_NODES) ? cnt[i] : 0;
    #pragma unroll
    for (int off = 16; off > 0; off >>= 1)
        v += __shfl_down_sync(0xffffffffu, v, off);
    __shared__ int w[16];
    if ((threadIdx.x & 31) == 0) w[threadIdx.x >> 5] = v;
    __syncthreads();
    if (threadIdx.x < 16) {
        int s = w[threadIdx.x];
        #pragma unroll
        for (int off = 8; off > 0; off >>= 1)
            s += __shfl_down_sync(0xffffu, s, off);
        if (threadIdx.x == 0) bsum[blockIdx.x] = s;
    }
}

// Phase 2+3 merged: every block scans the partials (redundant, cheap),
// takes its exclusive base, then scans its 512-node chunk. Emits rowptr+dinv.
__global__ __launch_bounds__(512) void k_scan3(const int* __restrict__ cnt,
                                               const int* __restrict__ bsum,
                                               int* __restrict__ rowptr,
                                               float* __restrict__ dinv) {
    __shared__ int s[512];
    __shared__ int base_sh;
    int t = threadIdx.x;

    int v = (t < SCAN_BLOCKS) ? bsum[t] : 0;
    s[t] = v;
    __syncthreads();
    #pragma unroll
    for (int off = 1; off < 512; off <<= 1) {
        int u = (t >= off) ? s[t - off] : 0;
        __syncthreads();
        s[t] += u;
        __syncthreads();
    }
    if (t == 0) base_sh = (blockIdx.x == 0) ? 0 : s[blockIdx.x - 1];
    __syncthreads();
    int base = base_sh;
    __syncthreads();

    int i = blockIdx.x * 512 + t;
    int c = (i < N_NODES) ? cnt[i] : 0;
    s[t] = c;
    __syncthreads();
    #pragma unroll
    for (int off = 1; off < 512; off <<= 1) {
        int u = (t >= off) ? s[t - off] : 0;
        __syncthreads();
        s[t] += u;
        __syncthreads();
    }
    if (i < N_NODES) {
        rowptr[i] = base + s[t] - c;   // exclusive
        dinv[i] = rsqrtf(1.0f + (float)c);
    }
    if (i == 0) rowptr[N_NODES] = N_EDGES;
}

// fill: consume cnt as cursors via atomicSub (cnt dead after scan3).
__global__ void k_fill(const int* __restrict__ EI,
                       const int* __restrict__ rowptr,
                       int* __restrict__ cnt,
                       int* __restrict__ col,
                       const int* __restrict__ flag) {
    int e = blockIdx.x * blockDim.x + threadIdx.x;
    if (e < N_EDGES) {
        int is64 = *flag;
        int s = edge_src(EI, e, is64);
        int d = edge_dst(EI, e, is64);
        int p = rowptr[d] + atomicSub(&cnt[d], 1) - 1;
        col[p] = s;
    }
}

// ---------------------------------------------------------------------------
// Tensor-core GEMM: Yh[r] = half( (in[r] @ W) * dinv[r] )
// mma.sync.m16n8k16 fp16 x fp16 -> fp32. 128 rows/block, 8 warps:
// warp w computes rows [w*16, w*16+16) x all 64 cols (8 n-tiles x 4 k-chunks).
__global__ __launch_bounds__(256) void k_gemm(const float* __restrict__ in,
                                              const float* __restrict__ W,
                                              const float* __restrict__ dinv,
                                              __half* __restrict__ Yh) {
    __shared__ __align__(16) __half At[GEMM_ROWS][66];  // X tile, fp16, padded
    __shared__ __align__(16) __half Wt[64][66];         // W transposed [n][k]

    const int tid = threadIdx.x;
    const int row0 = blockIdx.x * GEMM_ROWS;

    // Load + convert X rows (each thread: half a row = 32 floats)
    {
        int r = tid >> 1;
        int c0 = (tid & 1) * 32;
        const float4* src = (const float4*)(in + (size_t)(row0 + r) * FDIM + c0);
        #pragma unroll
        for (int i = 0; i < 8; i++) {
            float4 v = src[i];
            *(__half2*)&At[r][c0 + i * 4]     = __floats2half2_rn(v.x, v.y);
            *(__half2*)&At[r][c0 + i * 4 + 2] = __floats2half2_rn(v.z, v.w);
        }
    }
    // Load + convert + transpose W: Wt[n][k] = W[k][n]
    {
        #pragma unroll
        for (int i = 0; i < 16; i++) {
            int idx = i * 256 + tid;       // coalesced read
            int k = idx >> 6, n = idx & 63;
            Wt[n][k] = __float2half(W[idx]);
        }
    }
    __syncthreads();

    const int wid = tid >> 5, lane = tid & 31;
    const int g = lane >> 2, tc = lane & 3;
    const int rbase = wid * 16;

    float c[8][4];
    #pragma unroll
    for (int n8 = 0; n8 < 8; n8++)
        #pragma unroll
        for (int q = 0; q < 4; q++) c[n8][q] = 0.f;

    #pragma unroll
    for (int kc = 0; kc < 64; kc += 16) {
        unsigned a0 = *(const unsigned*)&At[rbase + g][tc * 2 + kc];
        unsigned a1 = *(const unsigned*)&At[rbase + g + 8][tc * 2 + kc];
        unsigned a2 = *(const unsigned*)&At[rbase + g][tc * 2 + kc + 8];
        unsigned a3 = *(const unsigned*)&At[rbase + g + 8][tc * 2 + kc + 8];
        #pragma unroll
        for (int n8 = 0; n8 < 8; n8++) {
            unsigned b0 = *(const unsigned*)&Wt[n8 * 8 + g][tc * 2 + kc];
            unsigned b1 = *(const unsigned*)&Wt[n8 * 8 + g][tc * 2 + kc + 8];
            asm volatile(
                "mma.sync.aligned.m16n8k16.row.col.f32.f16.f16.f32 "
                "{%0,%1,%2,%3}, {%4,%5,%6,%7}, {%8,%9}, {%0,%1,%2,%3};\n"
                : "+f"(c[n8][0]), "+f"(c[n8][1]), "+f"(c[n8][2]), "+f"(c[n8][3])
                : "r"(a0), "r"(a1), "r"(a2), "r"(a3), "r"(b0), "r"(b1));
        }
    }

    // Epilogue: scale by dinv, convert, store.
    int r0 = row0 + rbase + g;
    int r1 = r0 + 8;
    float dv0 = dinv[r0];
    float dv1 = dinv[r1];
    #pragma unroll
    for (int n8 = 0; n8 < 8; n8++) {
        int colc = n8 * 8 + tc * 2;
        *(__half2*)&Yh[(size_t)r0 * FDIM + colc] =
            __floats2half2_rn(c[n8][0] * dv0, c[n8][1] * dv0);
        *(__half2*)&Yh[(size_t)r1 * FDIM + colc] =
            __floats2half2_rn(c[n8][2] * dv1, c[n8][3] * dv1);
    }
}

// ---------------------------------------------------------------------------
// Aggregation: one warp per node; fp16 gather payload, fp32 accumulate.
//   out[i] = maybe_relu( dinv[i] * ( Y[i] + sum_{src in CSR[i]} Y[src] ) + b )
__global__ __launch_bounds__(256) void k_agg(const __half* __restrict__ Yh,
                                             const int* __restrict__ rowptr,
                                             const int* __restrict__ col,
                                             const float* __restrict__ dinv,
                                             const float* __restrict__ bias,
                                             float* __restrict__ out,
                                             int do_relu) {
    int gw = (blockIdx.x * blockDim.x + threadIdx.x) >> 5;   // warp = node
    int lane = threadIdx.x & 31;
    if (gw >= N_NODES) return;

    const __half2* Y2 = (const __half2*)Yh;   // 32 half2 per row
    float2 a0 = __half22float2(Y2[(size_t)gw * 32 + lane]);  // self term
    float2 a1 = {0.f, 0.f}, a2 = {0.f, 0.f}, a3 = {0.f, 0.f};

    int beg = rowptr[gw];
    int end = rowptr[gw + 1];
    for (int j = beg; j < end; j += 32) {
        int idx = j + lane;
        int id = (idx < end) ? col[idx] : 0;
        int cnt = min(32, end - j);
        int t = 0;
        for (; t + 8 <= cnt; t += 8) {
            int s0 = __shfl_sync(0xffffffffu, id, t);
            int s1 = __shfl_sync(0xffffffffu, id, t + 1);
            int s2 = __shfl_sync(0xffffffffu, id, t + 2);
            int s3 = __shfl_sync(0xffffffffu, id, t + 3);
            int s4 = __shfl_sync(0xffffffffu, id, t + 4);
            int s5 = __shfl_sync(0xffffffffu, id, t + 5);
            int s6 = __shfl_sync(0xffffffffu, id, t + 6);
            int s7 = __shfl_sync(0xffffffffu, id, t + 7);
            __half2 h0 = Y2[(size_t)s0 * 32 + lane];
            __half2 h1 = Y2[(size_t)s1 * 32 + lane];
            __half2 h2 = Y2[(size_t)s2 * 32 + lane];
            __half2 h3 = Y2[(size_t)s3 * 32 + lane];
            __half2 h4 = Y2[(size_t)s4 * 32 + lane];
            __half2 h5 = Y2[(size_t)s5 * 32 + lane];
            __half2 h6 = Y2[(size_t)s6 * 32 + lane];
            __half2 h7 = Y2[(size_t)s7 * 32 + lane];
            float2 v0 = __half22float2(h0);
            float2 v1 = __half22float2(h1);
            float2 v2 = __half22float2(h2);
            float2 v3 = __half22float2(h3);
            float2 v4 = __half22float2(h4);
            float2 v5 = __half22float2(h5);
            float2 v6 = __half22float2(h6);
            float2 v7 = __half22float2(h7);
            a0.x += v0.x; a0.y += v0.y;
            a1.x += v1.x; a1.y += v1.y;
            a2.x += v2.x; a2.y += v2.y;
            a3.x += v3.x; a3.y += v3.y;
            a0.x += v4.x; a0.y += v4.y;
            a1.x += v5.x; a1.y += v5.y;
            a2.x += v6.x; a2.y += v6.y;
            a3.x += v7.x; a3.y += v7.y;
        }
        for (; t < cnt; t++) {
            int s0 = __shfl_sync(0xffffffffu, id, t);
            float2 v0 = __half22float2(Y2[(size_t)s0 * 32 + lane]);
            a0.x += v0.x; a0.y += v0.y;
        }
    }

    float2 acc;
    acc.x = (a0.x + a1.x) + (a2.x + a3.x);
    acc.y = (a0.y + a1.y) + (a2.y + a3.y);

    float dv = dinv[gw];
    float2 bv = ((const float2*)bias)[lane];
    float2 r;
    r.x = acc.x * dv + bv.x;
    r.y = acc.y * dv + bv.y;
    if (do_relu) {
        r.x = fmaxf(r.x, 0.0f);
        r.y = fmaxf(r.y, 0.0f);
    }
    ((float2*)out)[(size_t)gw * 32 + lane] = r;
}

// ---------------------------------------------------------------------------
extern "C" void kernel_launch(void* const* d_in, const int* in_sizes, int n_in,
                              void* d_out, int out_size) {
    const float* X  = (const float*)d_in[0];
    const int*   EI = (const int*)d_in[1];   // edge_index (int32; int64 auto-detected)
    const float* W1 = (const float*)d_in[2];
    const float* b1 = (const float*)d_in[3];
    const float* W2 = (const float*)d_in[4];
    const float* b2 = (const float*)d_in[5];
    const float* W3 = (const float*)d_in[6];
    const float* b3 = (const float*)d_in[7];
    float* out = (float*)d_out;

    void *pYh, *pA, *pDinv, *pCnt, *pRow, *pCol, *pFlag, *pBs;
    cudaGetSymbolAddress(&pYh, g_Yh);
    cudaGetSymbolAddress(&pA, g_A);
    cudaGetSymbolAddress(&pDinv, g_dinv);
    cudaGetSymbolAddress(&pCnt, g_cnt);
    cudaGetSymbolAddress(&pRow, g_rowptr);
    cudaGetSymbolAddress(&pCol, g_col);
    cudaGetSymbolAddress(&pFlag, g_is64);
    cudaGetSymbolAddress(&pBs, g_bsum);
    __half* Yh  = (__half*)pYh;
    float* Ab   = (float*)pA;
    float* dinv = (float*)pDinv;
    int*   cnt  = (int*)pCnt;
    int*   row  = (int*)pRow;
    int*   colA = (int*)pCol;
    int*   flag = (int*)pFlag;
    int*   bsum = (int*)pBs;

    const int nodeBlocks = (N_NODES + 255) / 256;         // 313
    const int edgeBlocks = (N_EDGES + 255) / 256;
    const int aggBlocks  = (N_NODES * 32 + 255) / 256;    // 10000 (warp/node)

    // --- structure build ---
    k_zero_detect<<<nodeBlocks, 256>>>(cnt, EI, flag);
    k_hist<<<edgeBlocks, 256>>>(EI, cnt, flag);
    k_scan1<<<SCAN_BLOCKS, 512>>>(cnt, bsum);
    k_scan3<<<SCAN_BLOCKS, 512>>>(cnt, bsum, row, dinv);
    k_fill<<<edgeBlocks, 256>>>(EI, row, cnt, colA, flag);

    // --- layer 1: X -> g_A ---
    k_gemm<<<GEMM_BLOCKS, 256>>>(X, W1, dinv, Yh);
    k_agg<<<aggBlocks, 256>>>(Yh, row, colA, dinv, b1, Ab, 1);

    // --- layer 2: g_A -> g_A ---
    k_gemm<<<GEMM_BLOCKS, 256>>>(Ab, W2, dinv, Yh);
    k_agg<<<aggBlocks, 256>>>(Yh, row, colA, dinv, b2, Ab, 1);

    // --- layer 3: g_A -> d_out (no relu) ---
    k_gemm<<<GEMM_BLOCKS, 256>>>(Ab, W3, dinv, Yh);
    k_agg<<<aggBlocks, 256>>>(Yh, row, colA, dinv, b3, out, 0);
}